// round 3
// baseline (speedup 1.0000x reference)
#include <cuda_runtime.h>
#include <math.h>

#define NN 4096
#define FF 512
#define NH 8
#define DH 64
#define NC 40
#define LRA 0.2f

// ---------------- scratch (__device__ globals; no allocs) ----------------
__device__ float g_Wh [NN*FF];                 // layer1 Wh: [N][H*DH]
__device__ float g_f1 [NH*NN], g_f2 [NH*NN];
__device__ float g_e1p[NH*NN], g_e1n[NH*NN], g_e2p[NH*NN], g_e2n[NH*NN];
__device__ float g_h1 [NN*FF];                 // layer1 output (post-ELU, concat)
__device__ float g_Wh2[NN*NC];
__device__ float g_f1b[NN], g_f2b[NN], g_e1pb[NN], g_e1nb[NN], g_e2pb[NN], g_e2nb[NN];
__device__ float g_out2[NN*NC];

// ---------------- packed f32x2 helpers ----------------
__device__ __forceinline__ unsigned long long dup2(float a){
    unsigned long long r;
    asm("mov.b64 %0, {%1, %1};" : "=l"(r) : "f"(a));
    return r;
}
__device__ __forceinline__ void fma2(unsigned long long &d, unsigned long long a, unsigned long long b){
    asm("fma.rn.f32x2 %0, %1, %2, %3;" : "=l"(d) : "l"(a), "l"(b), "l"(d));
}
__device__ __forceinline__ float2 unpk(unsigned long long v){
    float2 r;
    asm("mov.b64 {%0, %1}, %2;" : "=f"(r.x), "=f"(r.y) : "l"(v));
    return r;
}
__device__ __forceinline__ float elu1(float v){
    return v > 0.f ? v : expm1f(v);
}

// ================= kernel 1: Wh = x @ W1 (64x64 tiles, f32x2) =================
__global__ void k_gemm1(const float* __restrict__ x, const float* __restrict__ W1){
    __shared__ float As[64][65];
    __shared__ float Bs[64][64];
    int tx = threadIdx.x, ty = threadIdx.y;
    int tid = ty*16+tx;
    int i0 = blockIdx.x*64;
    int h  = blockIdx.y;
    unsigned long long acc[4][2] = {};
    for (int k0 = 0; k0 < FF; k0 += 64){
        __syncthreads();
        #pragma unroll
        for (int t = 0; t < 16; t++){
            int idx = tid + t*256;
            int r = idx>>6, c = idx&63;
            As[r][c] = x [(size_t)(i0+r)*FF + k0 + c];
            Bs[r][c] = W1[(size_t)h*FF*DH + (size_t)(k0+r)*DH + c];
        }
        __syncthreads();
        #pragma unroll 16
        for (int kk = 0; kk < 64; kk++){
            unsigned long long a0 = dup2(As[tx   ][kk]);
            unsigned long long a1 = dup2(As[tx+16][kk]);
            unsigned long long a2 = dup2(As[tx+32][kk]);
            unsigned long long a3 = dup2(As[tx+48][kk]);
            const unsigned long long* wr = (const unsigned long long*)&Bs[kk][0];
            unsigned long long b0 = wr[ty*2+0];
            unsigned long long b1 = wr[ty*2+1];
            fma2(acc[0][0],a0,b0); fma2(acc[0][1],a0,b1);
            fma2(acc[1][0],a1,b0); fma2(acc[1][1],a1,b1);
            fma2(acc[2][0],a2,b0); fma2(acc[2][1],a2,b1);
            fma2(acc[3][0],a3,b0); fma2(acc[3][1],a3,b1);
        }
    }
    #pragma unroll
    for (int i = 0; i < 4; i++){
        int row = i0 + tx + 16*i;
        float2 v0 = unpk(acc[i][0]);
        float2 v1 = unpk(acc[i][1]);
        float4 v = make_float4(v0.x, v0.y, v1.x, v1.y);
        *(float4*)&g_Wh[(size_t)row*FF + h*DH + ty*4] = v;
    }
}

// ====== kernel 2: f1,f2 + separable exp tables, layer 1 (one warp/(h,i)) ======
__global__ void k_f1(const float* __restrict__ a1){
    int g = blockIdx.x*8 + (threadIdx.x>>5);     // [0, 8*4096)
    int lane = threadIdx.x & 31;
    int h = g >> 12;
    int i = g & (NN-1);
    const float* wh = g_Wh + (size_t)i*FF + h*DH;
    const float* as = a1 + h*2*DH;
    const float* ad = as + DH;
    float p1 = wh[lane]*as[lane] + wh[lane+32]*as[lane+32];
    float p2 = wh[lane]*ad[lane] + wh[lane+32]*ad[lane+32];
    #pragma unroll
    for (int o = 16; o; o >>= 1){
        p1 += __shfl_xor_sync(0xffffffffu, p1, o);
        p2 += __shfl_xor_sync(0xffffffffu, p2, o);
    }
    if (lane == 0){
        int k = h*NN + i;
        g_f1 [k] = p1;            g_f2 [k] = p2;
        g_e1p[k] = __expf(p1);    g_e1n[k] = __expf(LRA*p1);
        g_e2p[k] = __expf(p2);    g_e2n[k] = __expf(LRA*p2);
    }
}

// === kernel 3: layer-1 masked-softmax attention + P@Wh GEMM (64x64 tiles) ===
// grid (head fastest = x, row-block = y) so all heads share adj rows in L2.
__global__ void k_att1(const int* __restrict__ adjm){
    __shared__ float Ps[64][65];
    __shared__ float Ws[64][64];
    __shared__ float f1s[64], e1ps[64], e1ns[64];
    __shared__ float f2s[64], e2ps[64], e2ns[64];
    __shared__ float denomS[64];
    int tx = threadIdx.x, ty = threadIdx.y;
    int tid = ty*16 + tx;              // 0..127
    int h  = blockIdx.x;
    int i0 = blockIdx.y*64;
    if (tid < 64){
        int i = i0 + tid;
        f1s [tid] = g_f1 [h*NN+i];
        e1ps[tid] = g_e1p[h*NN+i];
        e1ns[tid] = g_e1n[h*NN+i];
        denomS[tid] = 0.f;
    }
    unsigned long long acc[4][4] = {};
    for (int j0 = 0; j0 < NN; j0 += 64){
        __syncthreads();                               // prev MAC done
        if (tid < 64){
            int j = j0 + tid;
            f2s [tid] = g_f2 [h*NN+j];
            e2ps[tid] = g_e2p[h*NN+j];
            e2ns[tid] = g_e2n[h*NN+j];
        }
        #pragma unroll 8
        for (int t = 0; t < 32; t++){
            int idx = tid + t*128;
            int r = idx>>6, c = idx&63;
            Ws[r][c] = g_Wh[(size_t)(j0+r)*FF + h*DH + c];
        }
        __syncthreads();                               // f2 stage ready
        #pragma unroll 8
        for (int t = 0; t < 32; t++){
            int idx = tid + t*128;
            int r = idx>>6, jj = idx&63;
            int a = adjm[(size_t)(i0+r)*NN + j0 + jj];
            float s = f1s[r] + f2s[jj];
            float v = 0.f;
            if (a) v = (s >= 0.f) ? e1ps[r]*e2ps[jj] : e1ns[r]*e2ns[jj];
            Ps[r][jj] = v;
        }
        __syncthreads();                               // P tile ready
        if (tid < 64){
            float sm = 0.f;
            #pragma unroll 16
            for (int jj = 0; jj < 64; jj++) sm += Ps[tid][jj];
            denomS[tid] += sm;
        }
        #pragma unroll 8
        for (int kk = 0; kk < 64; kk++){
            unsigned long long a0 = dup2(Ps[tx   ][kk]);
            unsigned long long a1 = dup2(Ps[tx+16][kk]);
            unsigned long long a2 = dup2(Ps[tx+32][kk]);
            unsigned long long a3 = dup2(Ps[tx+48][kk]);
            const unsigned long long* wr = (const unsigned long long*)&Ws[kk][0];
            unsigned long long b0 = wr[ty*4+0];
            unsigned long long b1 = wr[ty*4+1];
            unsigned long long b2 = wr[ty*4+2];
            unsigned long long b3 = wr[ty*4+3];
            fma2(acc[0][0],a0,b0); fma2(acc[0][1],a0,b1); fma2(acc[0][2],a0,b2); fma2(acc[0][3],a0,b3);
            fma2(acc[1][0],a1,b0); fma2(acc[1][1],a1,b1); fma2(acc[1][2],a1,b2); fma2(acc[1][3],a1,b3);
            fma2(acc[2][0],a2,b0); fma2(acc[2][1],a2,b1); fma2(acc[2][2],a2,b2); fma2(acc[2][3],a2,b3);
            fma2(acc[3][0],a3,b0); fma2(acc[3][1],a3,b1); fma2(acc[3][2],a3,b2); fma2(acc[3][3],a3,b3);
        }
    }
    __syncthreads();
    #pragma unroll
    for (int i = 0; i < 4; i++){
        int row = tx + 16*i;
        float inv = 1.0f / denomS[row];
        float* op = &g_h1[(size_t)(i0+row)*FF + h*DH + ty*8];
        #pragma unroll
        for (int jp = 0; jp < 4; jp++){
            float2 v = unpk(acc[i][jp]);
            v.x = elu1(v.x * inv);
            v.y = elu1(v.y * inv);
            *(float2*)(op + 2*jp) = v;
        }
    }
}

// ================= kernel 4: Wh2 = h1 @ Wo (4096x512x40) =================
__global__ void k_gemm2(const float* __restrict__ Wo){
    __shared__ float As[64][65];
    __shared__ float Bs[64][40];
    int tx = threadIdx.x, ty = threadIdx.y;
    int tid = ty*16+tx;                // block (16,10) = 160
    int i0 = blockIdx.x*64;
    float acc[4][4] = {};
    for (int k0 = 0; k0 < FF; k0 += 64){
        __syncthreads();
        for (int idx = tid; idx < 4096; idx += 160){
            int r = idx>>6, c = idx&63;
            As[r][c] = g_h1[(size_t)(i0+r)*FF + k0 + c];
        }
        for (int idx = tid; idx < 64*NC; idx += 160){
            int r = idx/NC, c = idx - r*NC;
            Bs[r][c] = Wo[(size_t)(k0+r)*NC + c];
        }
        __syncthreads();
        #pragma unroll 8
        for (int kk = 0; kk < 64; kk++){
            float a0 = As[tx][kk], a1 = As[tx+16][kk], a2 = As[tx+32][kk], a3 = As[tx+48][kk];
            float4 b = *(const float4*)&Bs[kk][ty*4];
            acc[0][0] += a0*b.x; acc[0][1] += a0*b.y; acc[0][2] += a0*b.z; acc[0][3] += a0*b.w;
            acc[1][0] += a1*b.x; acc[1][1] += a1*b.y; acc[1][2] += a1*b.z; acc[1][3] += a1*b.w;
            acc[2][0] += a2*b.x; acc[2][1] += a2*b.y; acc[2][2] += a2*b.z; acc[2][3] += a2*b.w;
            acc[3][0] += a3*b.x; acc[3][1] += a3*b.y; acc[3][2] += a3*b.z; acc[3][3] += a3*b.w;
        }
    }
    #pragma unroll
    for (int i = 0; i < 4; i++){
        int row = i0 + tx + 16*i;
        float4 v = make_float4(acc[i][0], acc[i][1], acc[i][2], acc[i][3]);
        *(float4*)&g_Wh2[(size_t)row*NC + ty*4] = v;
    }
}

// ====== kernel 5: layer-2 f/e tables (one warp per node, 40 dims) ======
__global__ void k_f2b(const float* __restrict__ ao){
    int g = blockIdx.x*8 + (threadIdx.x>>5);   // [0, 4096)
    int lane = threadIdx.x & 31;
    const float* w = g_Wh2 + (size_t)g*NC;
    float v  = w[lane];
    float p1 = v*ao[lane];
    float p2 = v*ao[NC+lane];
    if (lane < 8){
        float v2 = w[32+lane];
        p1 += v2*ao[32+lane];
        p2 += v2*ao[NC+32+lane];
    }
    #pragma unroll
    for (int o = 16; o; o >>= 1){
        p1 += __shfl_xor_sync(0xffffffffu, p1, o);
        p2 += __shfl_xor_sync(0xffffffffu, p2, o);
    }
    if (lane == 0){
        g_f1b [g] = p1;          g_f2b [g] = p2;
        g_e1pb[g] = __expf(p1);  g_e1nb[g] = __expf(LRA*p1);
        g_e2pb[g] = __expf(p2);  g_e2nb[g] = __expf(LRA*p2);
    }
}

// === kernel 6: layer-2 attention (32-row tiles, D=40) ===
__global__ void k_att2(const int* __restrict__ adjm){
    __shared__ float Ps[32][33];
    __shared__ float Ws[64][40];
    __shared__ float f1s[32], e1ps[32], e1ns[32];
    __shared__ float f2s[64], e2ps[64], e2ns[64];
    __shared__ float denomS[32];
    int tx = threadIdx.x, ty = threadIdx.y;
    int tid = ty*16 + tx;              // block (16,10) = 160
    int i0 = blockIdx.x*32;
    if (tid < 32){
        f1s [tid] = g_f1b [i0+tid];
        e1ps[tid] = g_e1pb[i0+tid];
        e1ns[tid] = g_e1nb[i0+tid];
        denomS[tid] = 0.f;
    }
    unsigned long long acc[2][2] = {};
    for (int j0 = 0; j0 < NN; j0 += 64){
        __syncthreads();
        if (tid < 64){
            f2s [tid] = g_f2b [j0+tid];
            e2ps[tid] = g_e2pb[j0+tid];
            e2ns[tid] = g_e2nb[j0+tid];
        }
        for (int idx = tid; idx < 64*NC; idx += 160){
            int r = idx/NC, c = idx - r*NC;
            Ws[r][c] = g_Wh2[(size_t)(j0+r)*NC + c];
        }
        __syncthreads();
        for (int idx = tid; idx < 32*64; idx += 160){
            int r = idx>>6, jj = idx&63;
            int a = adjm[(size_t)(i0+r)*NN + j0 + jj];
            float s = f1s[r] + f2s[jj];
            float v = 0.f;
            if (a) v = (s >= 0.f) ? e1ps[r]*e2ps[jj] : e1ns[r]*e2ns[jj];
            Ps[r][jj] = v;
        }
        __syncthreads();
        if (tid < 32){
            float sm = 0.f;
            #pragma unroll 16
            for (int jj = 0; jj < 64; jj++) sm += Ps[tid][jj];
            denomS[tid] += sm;
        }
        #pragma unroll 8
        for (int kk = 0; kk < 64; kk++){
            unsigned long long a0 = dup2(Ps[tx   ][kk]);
            unsigned long long a1 = dup2(Ps[tx+16][kk]);
            const unsigned long long* wr = (const unsigned long long*)&Ws[kk][0];
            unsigned long long b0 = wr[ty*2+0];
            unsigned long long b1 = wr[ty*2+1];
            fma2(acc[0][0],a0,b0); fma2(acc[0][1],a0,b1);
            fma2(acc[1][0],a1,b0); fma2(acc[1][1],a1,b1);
        }
    }
    __syncthreads();
    #pragma unroll
    for (int i = 0; i < 2; i++){
        int row = tx + 16*i;
        float inv = 1.0f / denomS[row];
        float* op = &g_out2[(size_t)(i0+row)*NC + ty*4];
        #pragma unroll
        for (int jp = 0; jp < 2; jp++){
            float2 v = unpk(acc[i][jp]);
            v.x *= inv; v.y *= inv;
            *(float2*)(op + 2*jp) = v;
        }
    }
}

// ====== kernel 7: outer ELU + log_softmax (one warp per row) ======
__global__ void k_final(float* __restrict__ out){
    int w = threadIdx.x>>5, lane = threadIdx.x & 31;
    int i = blockIdx.x*8 + w;
    float v0 = elu1(g_out2[(size_t)i*NC + lane]);
    float v1 = (lane < 8) ? elu1(g_out2[(size_t)i*NC + 32 + lane]) : -1e30f;
    float m = fmaxf(v0, v1);
    #pragma unroll
    for (int o = 16; o; o >>= 1) m = fmaxf(m, __shfl_xor_sync(0xffffffffu, m, o));
    float s = expf(v0 - m) + ((lane < 8) ? expf(v1 - m) : 0.f);
    #pragma unroll
    for (int o = 16; o; o >>= 1) s += __shfl_xor_sync(0xffffffffu, s, o);
    float ls = m + logf(s);
    out[(size_t)i*NC + lane] = v0 - ls;
    if (lane < 8) out[(size_t)i*NC + 32 + lane] = v1 - ls;
}

// ============================== launch ==============================
extern "C" void kernel_launch(void* const* d_in, const int* in_sizes, int n_in,
                              void* d_out, int out_size){
    const float* x  = (const float*)d_in[0];
    const int*   adj= (const int*)  d_in[1];
    const float* W1 = (const float*)d_in[2];
    const float* a1 = (const float*)d_in[3];
    const float* Wo = (const float*)d_in[4];
    const float* ao = (const float*)d_in[5];
    float* out = (float*)d_out;

    const int* adj1 = adj + (size_t)NN*NN;   // adj[1] -> layer 1
    const int* adj0 = adj;                   // adj[0] -> layer 2

    k_gemm1<<<dim3(64, 8), dim3(16, 16)>>>(x, W1);
    k_f1   <<<4096, 256>>>(a1);
    k_att1 <<<dim3(8, 64), dim3(16, 8)>>>(adj1);   // head fastest -> adj L2 reuse
    k_gemm2<<<64, dim3(16, 10)>>>(Wo);
    k_f2b  <<<512, 256>>>(ao);
    k_att2 <<<128, dim3(16, 10)>>>(adj0);
    k_final<<<512, 256>>>(out);
}

// round 5
// speedup vs baseline: 1.8972x; 1.8972x over previous
#include <cuda_runtime.h>
#include <cuda_bf16.h>
#include <cstdint>
#include <math.h>

#define NN 4096
#define FF 512
#define NH 8
#define DH 64
#define NC 40
#define LRA 0.2f

// ---------------- scratch (__device__ globals; no allocs) ----------------
__device__ float g_Wh [NN*FF];                  // layer1 Wh fp32: [N][H*DH]
__device__ __nv_bfloat16 g_WhT_hi[NH*DH*NN];    // Wh^T hi bf16: [h][d][n]
__device__ __nv_bfloat16 g_WhT_lo[NH*DH*NN];    // Wh^T lo bf16
__device__ float4 g_t1[NH*NN];                  // {e1p, e1n, f1, 0}
__device__ float4 g_t2[NH*NN];                  // {e2p, e2n, f2, 0}
__device__ unsigned g_adjbit[NN*(NN/32)];       // packed adj[1]
__device__ float g_h1 [NN*FF];                  // layer1 out (post-ELU, concat)
__device__ float g_Wh2[NN*NC];
__device__ float g_f1b[NN], g_f2b[NN], g_e1pb[NN], g_e1nb[NN], g_e2pb[NN], g_e2nb[NN];
__device__ float g_out2[NN*NC];

// ---------------- helpers ----------------
__device__ __forceinline__ float elu1(float v){ return v > 0.f ? v : expm1f(v); }
// pack {e0 -> low16, e1 -> high16} as bf16x2
__device__ __forceinline__ uint32_t bf2pack(float e0, float e1){
    uint32_t r;
    asm("cvt.rn.bf16x2.f32 %0, %1, %2;" : "=r"(r) : "f"(e1), "f"(e0));
    return r;
}
__device__ __forceinline__ float bflow (uint32_t u){ return __uint_as_float(u << 16); }
__device__ __forceinline__ float bfhigh(uint32_t u){ return __uint_as_float(u & 0xFFFF0000u); }

// mma.sync m16n8k16 row.col f32.bf16.bf16.f32 (HMMA — supported on plain sm_103 target)
__device__ __forceinline__ void mma_bf16(float* d, const uint32_t* a, uint32_t b0, uint32_t b1){
    asm volatile("mma.sync.aligned.m16n8k16.row.col.f32.bf16.bf16.f32 "
        "{%0,%1,%2,%3}, {%4,%5,%6,%7}, {%8,%9}, {%0,%1,%2,%3};"
        : "+f"(d[0]), "+f"(d[1]), "+f"(d[2]), "+f"(d[3])
        : "r"(a[0]), "r"(a[1]), "r"(a[2]), "r"(a[3]), "r"(b0), "r"(b1));
}

// ================= kernel 0: pack adj[1] into bitmask =================
__global__ void k_pack(const int* __restrict__ adjm){
    int w = blockIdx.x*8 + (threadIdx.x>>5);         // 16384 warps
    int lane = threadIdx.x & 31;
    const int* src = adjm + (size_t)w*1024;
    unsigned* dst = g_adjbit + (size_t)w*32;
    #pragma unroll 4
    for (int k = 0; k < 32; k++){
        int v = src[k*32 + lane];
        unsigned m = __ballot_sync(0xffffffffu, v > 0);
        if (lane == 0) dst[k] = m;
    }
}

// ====== kernel 1: Wh = x @ W1 (plain FFMA) + fp32 store + bf16 hi/lo transpose ======
__global__ void k_gemm1(const float* __restrict__ x, const float* __restrict__ W1){
    __shared__ float As[64][65];
    __shared__ float Bs[64][64];
    int tx = threadIdx.x, ty = threadIdx.y;
    int tid = ty*16+tx;
    int i0 = blockIdx.x*64;
    int h  = blockIdx.y;
    float acc[4][4] = {};
    for (int k0 = 0; k0 < FF; k0 += 64){
        __syncthreads();
        #pragma unroll
        for (int t = 0; t < 16; t++){
            int idx = tid + t*256;
            int r = idx>>6, c = idx&63;
            As[r][c] = x [(size_t)(i0+r)*FF + k0 + c];
            Bs[r][c] = W1[(size_t)h*FF*DH + (size_t)(k0+r)*DH + c];
        }
        __syncthreads();
        #pragma unroll 8
        for (int kk = 0; kk < 64; kk++){
            float a0 = As[tx][kk], a1 = As[tx+16][kk], a2 = As[tx+32][kk], a3 = As[tx+48][kk];
            float4 b = *(const float4*)&Bs[kk][ty*4];
            acc[0][0]+=a0*b.x; acc[0][1]+=a0*b.y; acc[0][2]+=a0*b.z; acc[0][3]+=a0*b.w;
            acc[1][0]+=a1*b.x; acc[1][1]+=a1*b.y; acc[1][2]+=a1*b.z; acc[1][3]+=a1*b.w;
            acc[2][0]+=a2*b.x; acc[2][1]+=a2*b.y; acc[2][2]+=a2*b.z; acc[2][3]+=a2*b.w;
            acc[3][0]+=a3*b.x; acc[3][1]+=a3*b.y; acc[3][2]+=a3*b.z; acc[3][3]+=a3*b.w;
        }
    }
    __syncthreads();
    #pragma unroll
    for (int i = 0; i < 4; i++){
        int row = i0 + tx + 16*i;
        float4 v = make_float4(acc[i][0], acc[i][1], acc[i][2], acc[i][3]);
        *(float4*)&g_Wh[(size_t)row*FF + h*DH + ty*4] = v;
        #pragma unroll
        for (int q = 0; q < 4; q++) As[ty*4+q][tx+16*i] = acc[i][q];   // transpose stage
    }
    __syncthreads();
    {   // bf16 hi/lo transposed store: thread -> (d = tid/4, 16 consecutive i)
        int c = tid>>2, seg = (tid&3)*16;
        uint32_t hp[8], lp[8];
        #pragma unroll
        for (int e = 0; e < 8; e++){
            float v0 = As[c][seg+2*e], v1 = As[c][seg+2*e+1];
            uint32_t h2 = bf2pack(v0, v1);
            hp[e] = h2;
            lp[e] = bf2pack(v0 - bflow(h2), v1 - bfhigh(h2));
        }
        size_t base = (size_t)(h*64 + c)*NN + i0 + seg;
        *(uint4*)(g_WhT_hi + base)     = make_uint4(hp[0],hp[1],hp[2],hp[3]);
        *(uint4*)(g_WhT_hi + base + 8) = make_uint4(hp[4],hp[5],hp[6],hp[7]);
        *(uint4*)(g_WhT_lo + base)     = make_uint4(lp[0],lp[1],lp[2],lp[3]);
        *(uint4*)(g_WhT_lo + base + 8) = make_uint4(lp[4],lp[5],lp[6],lp[7]);
    }
}

// ====== kernel 2: layer-1 f/e tables (one warp per (h,i)) ======
__global__ void k_f1(const float* __restrict__ a1){
    int g = blockIdx.x*8 + (threadIdx.x>>5);
    int lane = threadIdx.x & 31;
    int h = g >> 12;
    int i = g & (NN-1);
    const float* wh = g_Wh + (size_t)i*FF + h*DH;
    const float* as = a1 + h*2*DH;
    const float* ad = as + DH;
    float p1 = wh[lane]*as[lane] + wh[lane+32]*as[lane+32];
    float p2 = wh[lane]*ad[lane] + wh[lane+32]*ad[lane+32];
    #pragma unroll
    for (int o = 16; o; o >>= 1){
        p1 += __shfl_xor_sync(0xffffffffu, p1, o);
        p2 += __shfl_xor_sync(0xffffffffu, p2, o);
    }
    if (lane == 0){
        int k = h*NN + i;
        g_t1[k] = make_float4(expf(p1), expf(LRA*p1), p1, 0.f);
        g_t2[k] = make_float4(expf(p2), expf(LRA*p2), p2, 0.f);
    }
}

// === kernel 3: layer-1 attention via mma.sync bf16 hi/lo (HMMA) ===
// Block: (head, 128 rows). 8 warps, each owns 16 rows (one m16 fragment row).
// P entries are computed directly in A-fragment layout (never hit SMEM).
// B (Wh^T hi/lo) staged fragment-ordered: one LDS.64 per mma operand.
#define PV(tt, e1p, e1n, f1, w, bit, out) { \
    float s_ = (f1) + (tt).z; \
    float v_ = (s_ >= 0.f) ? (e1p)*(tt).x : (e1n)*(tt).y; \
    out = (((w) >> (bit)) & 1u) ? v_ : 0.f; }

__global__ void __launch_bounds__(256) k_att1_mma(){
    __shared__ float4 s_tbl[128];
    __shared__ uint32_t s_adj[128][4];
    __shared__ uint2 Wf_hi[64][32];
    __shared__ uint2 Wf_lo[64][32];

    int tid = threadIdx.x, wid = tid>>5, lane = tid&31;
    int h = blockIdx.x, i0 = blockIdx.y*128;
    int tig = lane & 3;                       // thread-in-group (col pair)
    int r0l = wid*16 + (lane>>2);             // local row
    int r1l = r0l + 8;

    float4 t1a = g_t1[h*NN + i0 + r0l];
    float4 t1b = g_t1[h*NN + i0 + r1l];
    float e1p0=t1a.x, e1n0=t1a.y, f10=t1a.z;
    float e1p1=t1b.x, e1n1=t1b.y, f11=t1b.z;
    float ds0 = 0.f, ds1 = 0.f;

    float acc[8][4];
    #pragma unroll
    for (int nf = 0; nf < 8; nf++){ acc[nf][0]=acc[nf][1]=acc[nf][2]=acc[nf][3]=0.f; }

    for (int t = 0; t < 32; t++){
        int j0 = t*128;
        __syncthreads();
        if (tid < 128) s_tbl[tid] = g_t2[h*NN + j0 + tid];
        {
            int row = tid>>1, wsel = (tid&1)*2;
            uint2 w = *(const uint2*)(g_adjbit + (size_t)(i0+row)*128 + t*4 + wsel);
            s_adj[row][wsel] = w.x; s_adj[row][wsel+1] = w.y;
        }
        #pragma unroll
        for (int q = 0; q < 8; q++){
            int e = q*256 + tid;
            int fh = e>>5, ln = e&31;
            int c = fh>>3, nf = fh&7;
            int d = nf*8 + (ln>>2);
            int jj = c*16 + (ln&3)*2;
            size_t src = (size_t)(h*64 + d)*NN + j0 + jj;
            Wf_hi[fh][ln] = make_uint2(*(const uint32_t*)(g_WhT_hi + src),
                                       *(const uint32_t*)(g_WhT_hi + src + 8));
            Wf_lo[fh][ln] = make_uint2(*(const uint32_t*)(g_WhT_lo + src),
                                       *(const uint32_t*)(g_WhT_lo + src + 8));
        }
        __syncthreads();

        #pragma unroll 2
        for (int c = 0; c < 8; c++){
            int p0 = c*16 + tig*2;
            float4 ta = s_tbl[p0], tb = s_tbl[p0+1], tc = s_tbl[p0+8], td = s_tbl[p0+9];
            uint32_t w0 = s_adj[r0l][c>>1] >> ((c&1)*16);
            uint32_t w1 = s_adj[r1l][c>>1] >> ((c&1)*16);
            int b0 = tig*2, b1 = b0+1, b2 = b0+8, b3 = b0+9;

            float v00,v01,v02,v03, v10,v11,v12,v13;
            PV(ta,e1p0,e1n0,f10,w0,b0,v00); PV(tb,e1p0,e1n0,f10,w0,b1,v01);
            PV(tc,e1p0,e1n0,f10,w0,b2,v02); PV(td,e1p0,e1n0,f10,w0,b3,v03);
            PV(ta,e1p1,e1n1,f11,w1,b0,v10); PV(tb,e1p1,e1n1,f11,w1,b1,v11);
            PV(tc,e1p1,e1n1,f11,w1,b2,v12); PV(td,e1p1,e1n1,f11,w1,b3,v13);
            ds0 += (v00+v01)+(v02+v03);
            ds1 += (v10+v11)+(v12+v13);

            uint32_t ah[4], al[4];
            ah[0] = bf2pack(v00, v01); ah[1] = bf2pack(v10, v11);
            ah[2] = bf2pack(v02, v03); ah[3] = bf2pack(v12, v13);
            al[0] = bf2pack(v00 - bflow(ah[0]), v01 - bfhigh(ah[0]));
            al[1] = bf2pack(v10 - bflow(ah[1]), v11 - bfhigh(ah[1]));
            al[2] = bf2pack(v02 - bflow(ah[2]), v03 - bfhigh(ah[2]));
            al[3] = bf2pack(v12 - bflow(ah[3]), v13 - bfhigh(ah[3]));

            #pragma unroll
            for (int nf = 0; nf < 8; nf++){
                uint2 bh = Wf_hi[c*8+nf][lane];
                uint2 bl = Wf_lo[c*8+nf][lane];
                mma_bf16(acc[nf], ah, bh.x, bh.y);
                mma_bf16(acc[nf], ah, bl.x, bl.y);
                mma_bf16(acc[nf], al, bh.x, bh.y);
            }
        }
    }

    // denominators: reduce across the 4 lanes sharing a row
    ds0 += __shfl_xor_sync(0xffffffffu, ds0, 1);
    ds0 += __shfl_xor_sync(0xffffffffu, ds0, 2);
    ds1 += __shfl_xor_sync(0xffffffffu, ds1, 1);
    ds1 += __shfl_xor_sync(0xffffffffu, ds1, 2);
    float inv0 = 1.0f / ds0, inv1 = 1.0f / ds1;

    float* base0 = &g_h1[(size_t)(i0+r0l)*FF + h*DH + tig*2];
    float* base1 = &g_h1[(size_t)(i0+r1l)*FF + h*DH + tig*2];
    #pragma unroll
    for (int nf = 0; nf < 8; nf++){
        float2 o0 = make_float2(elu1(acc[nf][0]*inv0), elu1(acc[nf][1]*inv0));
        float2 o1 = make_float2(elu1(acc[nf][2]*inv1), elu1(acc[nf][3]*inv1));
        *(float2*)(base0 + nf*8) = o0;
        *(float2*)(base1 + nf*8) = o1;
    }
}

// ================= kernel 4: Wh2 = h1 @ Wo (32-row blocks) =================
__global__ void k_gemm2(const float* __restrict__ Wo){
    __shared__ float As[32][65];
    __shared__ float Bs[64][40];
    int tid = threadIdx.x;
    int row = tid & 31, cg = tid >> 5;      // 8 col-groups x 5 cols
    int i0 = blockIdx.x*32;
    float acc[5] = {};
    for (int k0 = 0; k0 < FF; k0 += 64){
        __syncthreads();
        #pragma unroll
        for (int t = 0; t < 8; t++){
            int idx = tid + t*256;
            int rr = idx>>6, c = idx&63;
            As[rr&31][c] = (idx < 2048) ? g_h1[(size_t)(i0+(idx>>6))*FF + k0 + c] : As[rr&31][c];
        }
        for (int idx = tid; idx < 64*NC; idx += 256){
            int rr = idx/NC, c = idx - rr*NC;
            Bs[rr][c] = Wo[(size_t)(k0+rr)*NC + c];
        }
        __syncthreads();
        #pragma unroll 8
        for (int kk = 0; kk < 64; kk++){
            float a = As[row][kk];
            #pragma unroll
            for (int q = 0; q < 5; q++) acc[q] += a * Bs[kk][cg*5+q];
        }
    }
    #pragma unroll
    for (int q = 0; q < 5; q++)
        g_Wh2[(size_t)(i0+row)*NC + cg*5 + q] = acc[q];
}

// ====== kernel 5: layer-2 f/e tables ======
__global__ void k_f2b(const float* __restrict__ ao){
    int g = blockIdx.x*8 + (threadIdx.x>>5);
    int lane = threadIdx.x & 31;
    const float* w = g_Wh2 + (size_t)g*NC;
    float v  = w[lane];
    float p1 = v*ao[lane];
    float p2 = v*ao[NC+lane];
    if (lane < 8){
        float v2 = w[32+lane];
        p1 += v2*ao[32+lane];
        p2 += v2*ao[NC+32+lane];
    }
    #pragma unroll
    for (int o = 16; o; o >>= 1){
        p1 += __shfl_xor_sync(0xffffffffu, p1, o);
        p2 += __shfl_xor_sync(0xffffffffu, p2, o);
    }
    if (lane == 0){
        g_f1b [g] = p1;          g_f2b [g] = p2;
        g_e1pb[g] = expf(p1);    g_e1nb[g] = expf(LRA*p1);
        g_e2pb[g] = expf(p2);    g_e2nb[g] = expf(LRA*p2);
    }
}

// === kernel 6: layer-2 attention (plain FFMA, 32-row tiles, D=40) ===
__global__ void k_att2(const int* __restrict__ adjm){
    __shared__ float Ps[32][33];
    __shared__ float Ws[64][40];
    __shared__ float f1s[32], e1ps[32], e1ns[32];
    __shared__ float f2s[64], e2ps[64], e2ns[64];
    __shared__ float denomS[32];
    int tx = threadIdx.x, ty = threadIdx.y;
    int tid = ty*16 + tx;              // block (16,10) = 160
    int i0 = blockIdx.x*32;
    if (tid < 32){
        f1s [tid] = g_f1b [i0+tid];
        e1ps[tid] = g_e1pb[i0+tid];
        e1ns[tid] = g_e1nb[i0+tid];
        denomS[tid] = 0.f;
    }
    float acc[2][4] = {};
    for (int j0 = 0; j0 < NN; j0 += 64){
        __syncthreads();
        if (tid < 64){
            f2s [tid] = g_f2b [j0+tid];
            e2ps[tid] = g_e2pb[j0+tid];
            e2ns[tid] = g_e2nb[j0+tid];
        }
        for (int idx = tid; idx < 64*NC; idx += 160){
            int rr = idx/NC, c = idx - rr*NC;
            Ws[rr][c] = g_Wh2[(size_t)(j0+rr)*NC + c];
        }
        __syncthreads();
        for (int idx = tid; idx < 32*64; idx += 160){
            int rr = idx>>6, jj = idx&63;
            int a = adjm[(size_t)(i0+rr)*NN + j0 + jj];
            float s = f1s[rr] + f2s[jj];
            float v = 0.f;
            if (a) v = (s >= 0.f) ? e1ps[rr]*e2ps[jj] : e1ns[rr]*e2ns[jj];
            Ps[rr][jj] = v;
        }
        __syncthreads();
        if (tid < 32){
            float sm = 0.f;
            #pragma unroll 16
            for (int jj = 0; jj < 64; jj++) sm += Ps[tid][jj];
            denomS[tid] += sm;
        }
        #pragma unroll 8
        for (int kk = 0; kk < 64; kk++){
            float a0 = Ps[tx][kk], a1 = Ps[tx+16][kk];
            float4 b = *(const float4*)&Ws[kk][ty*4];
            acc[0][0]+=a0*b.x; acc[0][1]+=a0*b.y; acc[0][2]+=a0*b.z; acc[0][3]+=a0*b.w;
            acc[1][0]+=a1*b.x; acc[1][1]+=a1*b.y; acc[1][2]+=a1*b.z; acc[1][3]+=a1*b.w;
        }
    }
    __syncthreads();
    #pragma unroll
    for (int i = 0; i < 2; i++){
        int row = tx + 16*i;
        float inv = 1.0f / denomS[row];
        float4 v = make_float4(acc[i][0]*inv, acc[i][1]*inv, acc[i][2]*inv, acc[i][3]*inv);
        *(float4*)&g_out2[(size_t)(i0+row)*NC + ty*4] = v;
    }
}

// ====== kernel 7: outer ELU + log_softmax (one warp per row) ======
__global__ void k_final(float* __restrict__ out){
    int w = threadIdx.x>>5, lane = threadIdx.x & 31;
    int i = blockIdx.x*8 + w;
    float v0 = elu1(g_out2[(size_t)i*NC + lane]);
    float v1 = (lane < 8) ? elu1(g_out2[(size_t)i*NC + 32 + lane]) : -1e30f;
    float m = fmaxf(v0, v1);
    #pragma unroll
    for (int o = 16; o; o >>= 1) m = fmaxf(m, __shfl_xor_sync(0xffffffffu, m, o));
    float s = expf(v0 - m) + ((lane < 8) ? expf(v1 - m) : 0.f);
    #pragma unroll
    for (int o = 16; o; o >>= 1) s += __shfl_xor_sync(0xffffffffu, s, o);
    float ls = m + logf(s);
    out[(size_t)i*NC + lane] = v0 - ls;
    if (lane < 8) out[(size_t)i*NC + 32 + lane] = v1 - ls;
}

// ============================== launch ==============================
extern "C" void kernel_launch(void* const* d_in, const int* in_sizes, int n_in,
                              void* d_out, int out_size){
    const float* x  = (const float*)d_in[0];
    const int*   adj= (const int*)  d_in[1];
    const float* W1 = (const float*)d_in[2];
    const float* a1 = (const float*)d_in[3];
    const float* Wo = (const float*)d_in[4];
    const float* ao = (const float*)d_in[5];
    float* out = (float*)d_out;

    const int* adj1 = adj + (size_t)NN*NN;   // adj[1] -> layer 1
    const int* adj0 = adj;                   // adj[0] -> layer 2

    k_pack <<<2048, 256>>>(adj1);
    k_gemm1<<<dim3(64, 8), dim3(16, 16)>>>(x, W1);
    k_f1   <<<4096, 256>>>(a1);
    k_att1_mma<<<dim3(8, 32), 256>>>();
    k_gemm2<<<128, 256>>>(Wo);
    k_f2b  <<<512, 256>>>(ao);
    k_att2 <<<128, dim3(16, 10)>>>(adj0);
    k_final<<<512, 256>>>(out);
}

// round 6
// speedup vs baseline: 3.6445x; 1.9210x over previous
#include <cuda_runtime.h>
#include <cuda_bf16.h>
#include <cstdint>
#include <math.h>

#define NN 4096
#define FF 512
#define NH 8
#define DH 64
#define NC 40
#define LRA 0.2f

// ---------------- scratch (__device__ globals; no allocs) ----------------
__device__ float g_Wh [NN*FF];                  // layer1 Wh fp32: [N][H*DH]
__device__ __nv_bfloat16 g_WhT_hi[NH*DH*NN];    // Wh^T hi bf16: [h][d][n]
__device__ __nv_bfloat16 g_WhT_lo[NH*DH*NN];    // Wh^T lo bf16
__device__ float4 g_t1[NH*NN];                  // {e1p, e1n, f1, 0}
__device__ float4 g_t2[NH*NN];                  // {e2p, e2n, f2, 0}
__device__ unsigned g_adjbit [NN*(NN/32)];      // packed adj[1] (layer 1)
__device__ unsigned g_adjbit2[NN*(NN/32)];      // packed adj[0] (layer 2)
__device__ float g_h1 [NN*FF];                  // layer1 out (post-ELU, concat)
__device__ float g_Wh2[NN*NC];
__device__ __nv_bfloat16 g_W2T_hi[NC*NN];       // Wh2^T hi bf16: [d][n]
__device__ __nv_bfloat16 g_W2T_lo[NC*NN];
__device__ float4 g_t1b[NN], g_t2b[NN];
__device__ float g_out2[NN*NC];

// ---------------- helpers ----------------
__device__ __forceinline__ float elu1(float v){ return v > 0.f ? v : expm1f(v); }
__device__ __forceinline__ uint32_t bf2pack(float e0, float e1){
    uint32_t r;
    asm("cvt.rn.bf16x2.f32 %0, %1, %2;" : "=r"(r) : "f"(e1), "f"(e0));
    return r;
}
__device__ __forceinline__ float bflow (uint32_t u){ return __uint_as_float(u << 16); }
__device__ __forceinline__ float bfhigh(uint32_t u){ return __uint_as_float(u & 0xFFFF0000u); }

__device__ __forceinline__ void mma_bf16(float* d, const uint32_t* a, uint32_t b0, uint32_t b1){
    asm volatile("mma.sync.aligned.m16n8k16.row.col.f32.bf16.bf16.f32 "
        "{%0,%1,%2,%3}, {%4,%5,%6,%7}, {%8,%9}, {%0,%1,%2,%3};"
        : "+f"(d[0]), "+f"(d[1]), "+f"(d[2]), "+f"(d[3])
        : "r"(a[0]), "r"(a[1]), "r"(a[2]), "r"(a[3]), "r"(b0), "r"(b1));
}

#define PV(tt, e1p_, e1n_, f1_, w, bit, out) { \
    float s_ = (f1_) + (tt).z; \
    float v_ = (s_ >= 0.f) ? (e1p_)*(tt).x : (e1n_)*(tt).y; \
    out = (((w) >> (bit)) & 1u) ? v_ : 0.f; }

// ================= kernel 0: pack adjacency into bitmasks (both layers) ===========
__global__ void k_pack(const int* __restrict__ adjm){
    int layer = blockIdx.y;                          // 0 -> adj[1], 1 -> adj[0]
    const int* base = adjm + (layer ? 0 : (size_t)NN*NN);
    unsigned* dstA  = layer ? g_adjbit2 : g_adjbit;
    int w = blockIdx.x*8 + (threadIdx.x>>5);         // 16384 warp-rows
    int lane = threadIdx.x & 31;
    const int* src = base + (size_t)w*1024;
    unsigned* dst = dstA + (size_t)w*32;
    #pragma unroll 4
    for (int k = 0; k < 32; k++){
        int v = src[k*32 + lane];
        unsigned m = __ballot_sync(0xffffffffu, v > 0);
        if (lane == 0) dst[k] = m;
    }
}

// ====== kernel 1: Wh = x @ W1 (scalar FFMA) + fp32 store + bf16 hi/lo transpose ======
__global__ void k_gemm1(const float* __restrict__ x, const float* __restrict__ W1){
    __shared__ float As[64][65];
    __shared__ float Bs[64][64];
    int tx = threadIdx.x, ty = threadIdx.y;
    int tid = ty*16+tx;
    int i0 = blockIdx.x*64;
    int h  = blockIdx.y;
    float acc[4][4] = {};
    for (int k0 = 0; k0 < FF; k0 += 64){
        __syncthreads();
        #pragma unroll
        for (int t = 0; t < 16; t++){
            int idx = tid + t*256;
            int r = idx>>6, c = idx&63;
            As[r][c] = x [(size_t)(i0+r)*FF + k0 + c];
            Bs[r][c] = W1[(size_t)h*FF*DH + (size_t)(k0+r)*DH + c];
        }
        __syncthreads();
        #pragma unroll 8
        for (int kk = 0; kk < 64; kk++){
            float a0 = As[tx][kk], a1 = As[tx+16][kk], a2 = As[tx+32][kk], a3 = As[tx+48][kk];
            float4 b = *(const float4*)&Bs[kk][ty*4];
            acc[0][0]+=a0*b.x; acc[0][1]+=a0*b.y; acc[0][2]+=a0*b.z; acc[0][3]+=a0*b.w;
            acc[1][0]+=a1*b.x; acc[1][1]+=a1*b.y; acc[1][2]+=a1*b.z; acc[1][3]+=a1*b.w;
            acc[2][0]+=a2*b.x; acc[2][1]+=a2*b.y; acc[2][2]+=a2*b.z; acc[2][3]+=a2*b.w;
            acc[3][0]+=a3*b.x; acc[3][1]+=a3*b.y; acc[3][2]+=a3*b.z; acc[3][3]+=a3*b.w;
        }
    }
    __syncthreads();
    #pragma unroll
    for (int i = 0; i < 4; i++){
        int row = i0 + tx + 16*i;
        float4 v = make_float4(acc[i][0], acc[i][1], acc[i][2], acc[i][3]);
        *(float4*)&g_Wh[(size_t)row*FF + h*DH + ty*4] = v;
        #pragma unroll
        for (int q = 0; q < 4; q++) As[ty*4+q][tx+16*i] = acc[i][q];
    }
    __syncthreads();
    {
        int c = tid>>2, seg = (tid&3)*16;
        uint32_t hp[8], lp[8];
        #pragma unroll
        for (int e = 0; e < 8; e++){
            float v0 = As[c][seg+2*e], v1 = As[c][seg+2*e+1];
            uint32_t h2 = bf2pack(v0, v1);
            hp[e] = h2;
            lp[e] = bf2pack(v0 - bflow(h2), v1 - bfhigh(h2));
        }
        size_t base = (size_t)(h*64 + c)*NN + i0 + seg;
        *(uint4*)(g_WhT_hi + base)     = make_uint4(hp[0],hp[1],hp[2],hp[3]);
        *(uint4*)(g_WhT_hi + base + 8) = make_uint4(hp[4],hp[5],hp[6],hp[7]);
        *(uint4*)(g_WhT_lo + base)     = make_uint4(lp[0],lp[1],lp[2],lp[3]);
        *(uint4*)(g_WhT_lo + base + 8) = make_uint4(lp[4],lp[5],lp[6],lp[7]);
    }
}

// ====== kernel 2: layer-1 f/e tables ======
__global__ void k_f1(const float* __restrict__ a1){
    int g = blockIdx.x*8 + (threadIdx.x>>5);
    int lane = threadIdx.x & 31;
    int h = g >> 12;
    int i = g & (NN-1);
    const float* wh = g_Wh + (size_t)i*FF + h*DH;
    const float* as = a1 + h*2*DH;
    const float* ad = as + DH;
    float p1 = wh[lane]*as[lane] + wh[lane+32]*as[lane+32];
    float p2 = wh[lane]*ad[lane] + wh[lane+32]*ad[lane+32];
    #pragma unroll
    for (int o = 16; o; o >>= 1){
        p1 += __shfl_xor_sync(0xffffffffu, p1, o);
        p2 += __shfl_xor_sync(0xffffffffu, p2, o);
    }
    if (lane == 0){
        int k = h*NN + i;
        g_t1[k] = make_float4(expf(p1), expf(LRA*p1), p1, 0.f);
        g_t2[k] = make_float4(expf(p2), expf(LRA*p2), p2, 0.f);
    }
}

// === kernel 3: layer-1 attention, HMMA bf16 hi/lo. 256 rows/block, 32 rows/warp ===
__global__ void __launch_bounds__(256) k_att1_mma(){
    __shared__ float4 s_tbl[128];
    __shared__ uint4 s_adj[256];
    __shared__ uint2 Wf_hi[64][32];
    __shared__ uint2 Wf_lo[64][32];

    int tid = threadIdx.x, wid = tid>>5, lane = tid&31;
    int h = blockIdx.x, i0 = blockIdx.y*256;
    int tig = lane & 3;
    int rA = wid*32 + (lane>>2);              // local row of A-frag0 group 0

    float e1p[4], e1n[4], f1v[4], ds[4];
    #pragma unroll
    for (int k = 0; k < 4; k++){
        float4 tv = g_t1[h*NN + i0 + rA + 8*k];
        e1p[k] = tv.x; e1n[k] = tv.y; f1v[k] = tv.z; ds[k] = 0.f;
    }

    float acc[2][8][4];
    #pragma unroll
    for (int fr = 0; fr < 2; fr++)
        #pragma unroll
        for (int nf = 0; nf < 8; nf++)
            acc[fr][nf][0]=acc[fr][nf][1]=acc[fr][nf][2]=acc[fr][nf][3]=0.f;

    #pragma unroll 1
    for (int t = 0; t < 32; t++){
        int j0 = t*128;
        __syncthreads();
        if (tid < 128) s_tbl[tid] = g_t2[h*NN + j0 + tid];
        s_adj[tid] = *(const uint4*)(g_adjbit + (size_t)(i0+tid)*128 + t*4);
        #pragma unroll
        for (int q = 0; q < 8; q++){
            int e = q*256 + tid;
            int fh = e>>5, ln = e&31;
            int c = fh>>3, nf = fh&7;
            int d = nf*8 + (ln>>2);
            int jj = c*16 + (ln&3)*2;
            size_t src = (size_t)(h*64 + d)*NN + j0 + jj;
            Wf_hi[fh][ln] = make_uint2(*(const uint32_t*)(g_WhT_hi + src),
                                       *(const uint32_t*)(g_WhT_hi + src + 8));
            Wf_lo[fh][ln] = make_uint2(*(const uint32_t*)(g_WhT_lo + src),
                                       *(const uint32_t*)(g_WhT_lo + src + 8));
        }
        __syncthreads();

        #pragma unroll 2
        for (int c = 0; c < 8; c++){
            int p0 = c*16 + tig*2;
            float4 tc0 = s_tbl[p0], tc1 = s_tbl[p0+1], tc2 = s_tbl[p0+8], tc3 = s_tbl[p0+9];
            int b0 = tig*2, b1 = b0+1, b2 = b0+8, b3 = b0+9;

            float v[4][4];
            #pragma unroll
            for (int k = 0; k < 4; k++){
                uint32_t wb = ((const uint32_t*)&s_adj[rA + 8*k])[c>>1] >> ((c&1)*16);
                PV(tc0, e1p[k], e1n[k], f1v[k], wb, b0, v[k][0]);
                PV(tc1, e1p[k], e1n[k], f1v[k], wb, b1, v[k][1]);
                PV(tc2, e1p[k], e1n[k], f1v[k], wb, b2, v[k][2]);
                PV(tc3, e1p[k], e1n[k], f1v[k], wb, b3, v[k][3]);
                ds[k] += (v[k][0]+v[k][1]) + (v[k][2]+v[k][3]);
            }

            uint32_t ah0[4], al0[4], ah1[4], al1[4];
            ah0[0] = bf2pack(v[0][0], v[0][1]); ah0[1] = bf2pack(v[1][0], v[1][1]);
            ah0[2] = bf2pack(v[0][2], v[0][3]); ah0[3] = bf2pack(v[1][2], v[1][3]);
            ah1[0] = bf2pack(v[2][0], v[2][1]); ah1[1] = bf2pack(v[3][0], v[3][1]);
            ah1[2] = bf2pack(v[2][2], v[2][3]); ah1[3] = bf2pack(v[3][2], v[3][3]);
            al0[0] = bf2pack(v[0][0]-bflow(ah0[0]), v[0][1]-bfhigh(ah0[0]));
            al0[1] = bf2pack(v[1][0]-bflow(ah0[1]), v[1][1]-bfhigh(ah0[1]));
            al0[2] = bf2pack(v[0][2]-bflow(ah0[2]), v[0][3]-bfhigh(ah0[2]));
            al0[3] = bf2pack(v[1][2]-bflow(ah0[3]), v[1][3]-bfhigh(ah0[3]));
            al1[0] = bf2pack(v[2][0]-bflow(ah1[0]), v[2][1]-bfhigh(ah1[0]));
            al1[1] = bf2pack(v[3][0]-bflow(ah1[1]), v[3][1]-bfhigh(ah1[1]));
            al1[2] = bf2pack(v[2][2]-bflow(ah1[2]), v[2][3]-bfhigh(ah1[2]));
            al1[3] = bf2pack(v[3][2]-bflow(ah1[3]), v[3][3]-bfhigh(ah1[3]));

            #pragma unroll
            for (int nf = 0; nf < 8; nf++){
                uint2 bh = Wf_hi[c*8+nf][lane];
                uint2 bl = Wf_lo[c*8+nf][lane];
                mma_bf16(acc[0][nf], ah0, bh.x, bh.y);
                mma_bf16(acc[0][nf], ah0, bl.x, bl.y);
                mma_bf16(acc[0][nf], al0, bh.x, bh.y);
                mma_bf16(acc[1][nf], ah1, bh.x, bh.y);
                mma_bf16(acc[1][nf], ah1, bl.x, bl.y);
                mma_bf16(acc[1][nf], al1, bh.x, bh.y);
            }
        }
    }

    float inv[4];
    #pragma unroll
    for (int k = 0; k < 4; k++){
        ds[k] += __shfl_xor_sync(0xffffffffu, ds[k], 1);
        ds[k] += __shfl_xor_sync(0xffffffffu, ds[k], 2);
        inv[k] = 1.0f / ds[k];
    }

    #pragma unroll
    for (int fr = 0; fr < 2; fr++){
        float* base0 = &g_h1[(size_t)(i0 + rA + 16*fr)*FF + h*DH + tig*2];
        float* base1 = &g_h1[(size_t)(i0 + rA + 16*fr + 8)*FF + h*DH + tig*2];
        float ia = inv[2*fr], ib = inv[2*fr+1];
        #pragma unroll
        for (int nf = 0; nf < 8; nf++){
            float2 o0 = make_float2(elu1(acc[fr][nf][0]*ia), elu1(acc[fr][nf][1]*ia));
            float2 o1 = make_float2(elu1(acc[fr][nf][2]*ib), elu1(acc[fr][nf][3]*ib));
            *(float2*)(base0 + nf*8) = o0;
            *(float2*)(base1 + nf*8) = o1;
        }
    }
}

// ========== kernel 4: Wh2 = h1 @ Wo + fp32 store + bf16 hi/lo transpose ==========
__global__ void k_gemm2(const float* __restrict__ Wo){
    __shared__ float As[32][65];
    __shared__ float Bs[64][40];
    __shared__ float Ts[40][33];
    int tid = threadIdx.x;
    int row = tid & 31, cg = tid >> 5;      // 8 col-groups x 5 cols
    int i0 = blockIdx.x*32;
    float acc[5] = {};
    for (int k0 = 0; k0 < FF; k0 += 64){
        __syncthreads();
        #pragma unroll
        for (int t = 0; t < 8; t++){
            int idx = tid + t*256;
            int rr = idx>>6, c = idx&63;
            As[rr&31][c] = g_h1[(size_t)(i0+rr)*FF + k0 + c];
        }
        for (int idx = tid; idx < 64*NC; idx += 256){
            int rr = idx/NC, c = idx - rr*NC;
            Bs[rr][c] = Wo[(size_t)(k0+rr)*NC + c];
        }
        __syncthreads();
        #pragma unroll 8
        for (int kk = 0; kk < 64; kk++){
            float a = As[row][kk];
            #pragma unroll
            for (int q = 0; q < 5; q++) acc[q] += a * Bs[kk][cg*5+q];
        }
    }
    #pragma unroll
    for (int q = 0; q < 5; q++){
        g_Wh2[(size_t)(i0+row)*NC + cg*5 + q] = acc[q];
        Ts[cg*5+q][row] = acc[q];
    }
    __syncthreads();
    for (int e = tid; e < NC*32; e += 256){
        int d = e>>5, il = e&31;
        float v = Ts[d][il];
        __nv_bfloat16 hb = __float2bfloat16(v);
        __nv_bfloat16 lb = __float2bfloat16(v - __bfloat162float(hb));
        g_W2T_hi[(size_t)d*NN + i0 + il] = hb;
        g_W2T_lo[(size_t)d*NN + i0 + il] = lb;
    }
}

// ====== kernel 5: layer-2 f/e tables (float4) ======
__global__ void k_f2b(const float* __restrict__ ao){
    int g = blockIdx.x*8 + (threadIdx.x>>5);
    int lane = threadIdx.x & 31;
    const float* w = g_Wh2 + (size_t)g*NC;
    float v  = w[lane];
    float p1 = v*ao[lane];
    float p2 = v*ao[NC+lane];
    if (lane < 8){
        float v2 = w[32+lane];
        p1 += v2*ao[32+lane];
        p2 += v2*ao[NC+32+lane];
    }
    #pragma unroll
    for (int o = 16; o; o >>= 1){
        p1 += __shfl_xor_sync(0xffffffffu, p1, o);
        p2 += __shfl_xor_sync(0xffffffffu, p2, o);
    }
    if (lane == 0){
        g_t1b[g] = make_float4(expf(p1), expf(LRA*p1), p1, 0.f);
        g_t2b[g] = make_float4(expf(p2), expf(LRA*p2), p2, 0.f);
    }
}

// === kernel 6: layer-2 attention, HMMA bf16 hi/lo (128 rows/block, 5 n-frags) ===
__global__ void __launch_bounds__(256) k_att2_mma(){
    __shared__ float4 s_tbl[128];
    __shared__ uint4 s_adj[128];
    __shared__ uint2 Wf_hi[40][32];
    __shared__ uint2 Wf_lo[40][32];

    int tid = threadIdx.x, wid = tid>>5, lane = tid&31;
    int i0 = blockIdx.x*128;
    int tig = lane & 3;
    int r0l = wid*16 + (lane>>2);
    int r1l = r0l + 8;

    float4 t1a = g_t1b[i0 + r0l];
    float4 t1b = g_t1b[i0 + r1l];
    float e1p0=t1a.x, e1n0=t1a.y, f10=t1a.z;
    float e1p1=t1b.x, e1n1=t1b.y, f11=t1b.z;
    float ds0 = 0.f, ds1 = 0.f;

    float acc[5][4];
    #pragma unroll
    for (int nf = 0; nf < 5; nf++){ acc[nf][0]=acc[nf][1]=acc[nf][2]=acc[nf][3]=0.f; }

    #pragma unroll 1
    for (int t = 0; t < 32; t++){
        int j0 = t*128;
        __syncthreads();
        if (tid < 128){
            s_tbl[tid] = g_t2b[j0 + tid];
            s_adj[tid] = *(const uint4*)(g_adjbit2 + (size_t)(i0+tid)*128 + t*4);
        }
        #pragma unroll
        for (int q = 0; q < 5; q++){
            int e = q*256 + tid;              // exactly 1280 = 40 frags x 32
            int fh = e>>5, ln = e&31;
            int nf = fh>>3, c = fh&7;
            int d = nf*8 + (ln>>2);
            int jj = c*16 + (ln&3)*2;
            size_t src = (size_t)d*NN + j0 + jj;
            Wf_hi[fh][ln] = make_uint2(*(const uint32_t*)(g_W2T_hi + src),
                                       *(const uint32_t*)(g_W2T_hi + src + 8));
            Wf_lo[fh][ln] = make_uint2(*(const uint32_t*)(g_W2T_lo + src),
                                       *(const uint32_t*)(g_W2T_lo + src + 8));
        }
        __syncthreads();

        #pragma unroll 2
        for (int c = 0; c < 8; c++){
            int p0 = c*16 + tig*2;
            float4 ta = s_tbl[p0], tb = s_tbl[p0+1], tc = s_tbl[p0+8], td = s_tbl[p0+9];
            uint32_t w0 = ((const uint32_t*)&s_adj[r0l])[c>>1] >> ((c&1)*16);
            uint32_t w1 = ((const uint32_t*)&s_adj[r1l])[c>>1] >> ((c&1)*16);
            int b0 = tig*2, b1 = b0+1, b2 = b0+8, b3 = b0+9;

            float v00,v01,v02,v03, v10,v11,v12,v13;
            PV(ta,e1p0,e1n0,f10,w0,b0,v00); PV(tb,e1p0,e1n0,f10,w0,b1,v01);
            PV(tc,e1p0,e1n0,f10,w0,b2,v02); PV(td,e1p0,e1n0,f10,w0,b3,v03);
            PV(ta,e1p1,e1n1,f11,w1,b0,v10); PV(tb,e1p1,e1n1,f11,w1,b1,v11);
            PV(tc,e1p1,e1n1,f11,w1,b2,v12); PV(td,e1p1,e1n1,f11,w1,b3,v13);
            ds0 += (v00+v01)+(v02+v03);
            ds1 += (v10+v11)+(v12+v13);

            uint32_t ah[4], al[4];
            ah[0] = bf2pack(v00, v01); ah[1] = bf2pack(v10, v11);
            ah[2] = bf2pack(v02, v03); ah[3] = bf2pack(v12, v13);
            al[0] = bf2pack(v00 - bflow(ah[0]), v01 - bfhigh(ah[0]));
            al[1] = bf2pack(v10 - bflow(ah[1]), v11 - bfhigh(ah[1]));
            al[2] = bf2pack(v02 - bflow(ah[2]), v03 - bfhigh(ah[2]));
            al[3] = bf2pack(v12 - bflow(ah[3]), v13 - bfhigh(ah[3]));

            #pragma unroll
            for (int nf = 0; nf < 5; nf++){
                uint2 bh = Wf_hi[nf*8+c][lane];
                uint2 bl = Wf_lo[nf*8+c][lane];
                mma_bf16(acc[nf], ah, bh.x, bh.y);
                mma_bf16(acc[nf], ah, bl.x, bl.y);
                mma_bf16(acc[nf], al, bh.x, bh.y);
            }
        }
    }

    ds0 += __shfl_xor_sync(0xffffffffu, ds0, 1);
    ds0 += __shfl_xor_sync(0xffffffffu, ds0, 2);
    ds1 += __shfl_xor_sync(0xffffffffu, ds1, 1);
    ds1 += __shfl_xor_sync(0xffffffffu, ds1, 2);
    float inv0 = 1.0f / ds0, inv1 = 1.0f / ds1;

    float* base0 = &g_out2[(size_t)(i0+r0l)*NC + tig*2];
    float* base1 = &g_out2[(size_t)(i0+r1l)*NC + tig*2];
    #pragma unroll
    for (int nf = 0; nf < 5; nf++){
        float2 o0 = make_float2(acc[nf][0]*inv0, acc[nf][1]*inv0);
        float2 o1 = make_float2(acc[nf][2]*inv1, acc[nf][3]*inv1);
        *(float2*)(base0 + nf*8) = o0;
        *(float2*)(base1 + nf*8) = o1;
    }
}

// ====== kernel 7: outer ELU + log_softmax (one warp per row) ======
__global__ void k_final(float* __restrict__ out){
    int w = threadIdx.x>>5, lane = threadIdx.x & 31;
    int i = blockIdx.x*8 + w;
    float v0 = elu1(g_out2[(size_t)i*NC + lane]);
    float v1 = (lane < 8) ? elu1(g_out2[(size_t)i*NC + 32 + lane]) : -1e30f;
    float m = fmaxf(v0, v1);
    #pragma unroll
    for (int o = 16; o; o >>= 1) m = fmaxf(m, __shfl_xor_sync(0xffffffffu, m, o));
    float s = expf(v0 - m) + ((lane < 8) ? expf(v1 - m) : 0.f);
    #pragma unroll
    for (int o = 16; o; o >>= 1) s += __shfl_xor_sync(0xffffffffu, s, o);
    float ls = m + logf(s);
    out[(size_t)i*NC + lane] = v0 - ls;
    if (lane < 8) out[(size_t)i*NC + 32 + lane] = v1 - ls;
}

// ============================== launch ==============================
extern "C" void kernel_launch(void* const* d_in, const int* in_sizes, int n_in,
                              void* d_out, int out_size){
    const float* x  = (const float*)d_in[0];
    const int*   adj= (const int*)  d_in[1];
    const float* W1 = (const float*)d_in[2];
    const float* a1 = (const float*)d_in[3];
    const float* Wo = (const float*)d_in[4];
    const float* ao = (const float*)d_in[5];
    float* out = (float*)d_out;

    k_pack <<<dim3(2048, 2), 256>>>(adj);
    k_gemm1<<<dim3(64, 8), dim3(16, 16)>>>(x, W1);
    k_f1   <<<4096, 256>>>(a1);
    k_att1_mma<<<dim3(8, 16), 256>>>();
    k_gemm2<<<128, 256>>>(Wo);
    k_f2b  <<<512, 256>>>(ao);
    k_att2_mma<<<32, 256>>>();
    k_final<<<512, 256>>>(out);
}

// round 7
// speedup vs baseline: 4.3433x; 1.1917x over previous
#include <cuda_runtime.h>
#include <cuda_bf16.h>
#include <cstdint>
#include <math.h>

#define NN 4096
#define FF 512
#define NH 8
#define DH 64
#define NC 40
#define LRA 0.2f

// ---------------- scratch (__device__ globals; no allocs) ----------------
__device__ float g_Wh [NN*FF];                  // layer1 Wh fp32: [N][H*DH]
__device__ uint4 g_xf_hi[(NN/16)*32*32];        // x A-frags hi: [(i16*32+c)*32+lane]
__device__ uint4 g_xf_lo[(NN/16)*32*32];
__device__ uint4 g_w1f[NH*32*8*32];             // W1 B-frags {bh01,bh89,bl01,bl89}
__device__ uint4 g_whf[NH*256*8*32];            // Wh^T B-frags for att1: [h][jc][nf][lane]
__device__ float4 g_t1[NH*NN];                  // {e1p, e1n, f1, 0}
__device__ float4 g_t2[NH*NN];
__device__ unsigned g_adjbit [NN*(NN/32)];      // packed adj[1] (layer 1)
__device__ unsigned g_adjbit2[NN*(NN/32)];      // packed adj[0] (layer 2)
__device__ float g_p1 [2*NN*FF];                // att1 partial acc (per j-half)
__device__ float g_pd1[2*NH*NN];                // att1 partial denom
__device__ float g_h1 [NN*FF];                  // layer1 out (post-ELU, concat)
__device__ float g_Wh2[NN*NC];
__device__ __nv_bfloat16 g_W2T_hi[NC*NN];       // Wh2^T hi bf16: [d][n]
__device__ __nv_bfloat16 g_W2T_lo[NC*NN];
__device__ float4 g_t1b[NN], g_t2b[NN];
__device__ float g_p2 [4*NN*NC];                // att2 partial acc
__device__ float g_pd2[4*NN];
__device__ float g_out2[NN*NC];

// ---------------- helpers ----------------
__device__ __forceinline__ float elu1(float v){ return v > 0.f ? v : expm1f(v); }
__device__ __forceinline__ uint32_t bf2pack(float e0, float e1){
    uint32_t r;
    asm("cvt.rn.bf16x2.f32 %0, %1, %2;" : "=r"(r) : "f"(e1), "f"(e0));
    return r;
}
__device__ __forceinline__ float bflow (uint32_t u){ return __uint_as_float(u << 16); }
__device__ __forceinline__ float bfhigh(uint32_t u){ return __uint_as_float(u & 0xFFFF0000u); }

__device__ __forceinline__ void mma_bf16(float* d, const uint32_t* a, uint32_t b0, uint32_t b1){
    asm volatile("mma.sync.aligned.m16n8k16.row.col.f32.bf16.bf16.f32 "
        "{%0,%1,%2,%3}, {%4,%5,%6,%7}, {%8,%9}, {%0,%1,%2,%3};"
        : "+f"(d[0]), "+f"(d[1]), "+f"(d[2]), "+f"(d[3])
        : "r"(a[0]), "r"(a[1]), "r"(a[2]), "r"(a[3]), "r"(b0), "r"(b1));
}

#define PV(tt, e1p_, e1n_, f1_, w, bit, out) { \
    float s_ = (f1_) + (tt).z; \
    float v_ = (s_ >= 0.f) ? (e1p_)*(tt).x : (e1n_)*(tt).y; \
    out = (((w) >> (bit)) & 1u) ? v_ : 0.f; }

// ================= kernel 0: pack adjacency into bitmasks (both layers) ===========
__global__ void k_pack(const int* __restrict__ adjm){
    int layer = blockIdx.y;                          // 0 -> adj[1], 1 -> adj[0]
    const int* base = adjm + (layer ? 0 : (size_t)NN*NN);
    unsigned* dstA  = layer ? g_adjbit2 : g_adjbit;
    int w = blockIdx.x*8 + (threadIdx.x>>5);
    int lane = threadIdx.x & 31;
    const int* src = base + (size_t)w*1024;
    unsigned* dst = dstA + (size_t)w*32;
    #pragma unroll 4
    for (int k = 0; k < 32; k++){
        int v = src[k*32 + lane];
        unsigned m = __ballot_sync(0xffffffffu, v > 0);
        if (lane == 0) dst[k] = m;
    }
}

// ====== kernel 0b: split x into hi/lo bf16 A-fragments ======
__global__ void k_xsplit(const float* __restrict__ x){
    int idx = blockIdx.x*256 + threadIdx.x;          // 262144
    int f = idx >> 5, lane = idx & 31;
    int i16 = f >> 5, c = f & 31;
    int r  = i16*16 + (lane>>2);
    int k0 = c*16 + (lane&3)*2;
    float2 p00 = *(const float2*)(x + (size_t)r*FF + k0);
    float2 p10 = *(const float2*)(x + (size_t)(r+8)*FF + k0);
    float2 p01 = *(const float2*)(x + (size_t)r*FF + k0 + 8);
    float2 p11 = *(const float2*)(x + (size_t)(r+8)*FF + k0 + 8);
    uint32_t a0 = bf2pack(p00.x, p00.y);
    uint32_t a1 = bf2pack(p10.x, p10.y);
    uint32_t a2 = bf2pack(p01.x, p01.y);
    uint32_t a3 = bf2pack(p11.x, p11.y);
    g_xf_hi[idx] = make_uint4(a0, a1, a2, a3);
    uint32_t l0 = bf2pack(p00.x - bflow(a0), p00.y - bfhigh(a0));
    uint32_t l1 = bf2pack(p10.x - bflow(a1), p10.y - bfhigh(a1));
    uint32_t l2 = bf2pack(p01.x - bflow(a2), p01.y - bfhigh(a2));
    uint32_t l3 = bf2pack(p11.x - bflow(a3), p11.y - bfhigh(a3));
    g_xf_lo[idx] = make_uint4(l0, l1, l2, l3);
}

// ====== kernel 0c: split W1 into hi/lo bf16 B-fragments ======
__global__ void k_w1split(const float* __restrict__ W1){
    int idx = blockIdx.x*256 + threadIdx.x;          // 65536
    int f = idx >> 5, lane = idx & 31;
    int h = f >> 8, rem = f & 255;
    int c = rem >> 3, nf = rem & 7;
    int k0 = c*16 + (lane&3)*2;
    int n  = nf*8 + (lane>>2);
    const float* Wb = W1 + (size_t)h*FF*DH;
    float w0 = Wb[(size_t)k0*DH + n];
    float w1 = Wb[(size_t)(k0+1)*DH + n];
    float w2 = Wb[(size_t)(k0+8)*DH + n];
    float w3 = Wb[(size_t)(k0+9)*DH + n];
    uint32_t h01 = bf2pack(w0, w1), h89 = bf2pack(w2, w3);
    uint32_t l01 = bf2pack(w0 - bflow(h01), w1 - bfhigh(h01));
    uint32_t l89 = bf2pack(w2 - bflow(h89), w3 - bfhigh(h89));
    g_w1f[idx] = make_uint4(h01, h89, l01, l89);
}

// ====== kernel 1: Wh = x @ W1 via HMMA hi/lo + epilogues (fp32 + att1 B-frags) ======
__global__ void __launch_bounds__(256, 2) k_gemm1h(){
    extern __shared__ float Ts[];                    // [256][68]
    int tid = threadIdx.x, wid = tid>>5, lane = tid&31;
    int i0 = blockIdx.x*256, h = blockIdx.y;
    int tig = lane & 3;
    int f0 = (i0>>4) + wid*2;

    float acc[2][8][4];
    #pragma unroll
    for (int fr = 0; fr < 2; fr++)
        #pragma unroll
        for (int nf = 0; nf < 8; nf++)
            acc[fr][nf][0]=acc[fr][nf][1]=acc[fr][nf][2]=acc[fr][nf][3]=0.f;

    #pragma unroll 2
    for (int c = 0; c < 32; c++){
        uint4 AH0 = g_xf_hi[(f0*32 + c)*32 + lane];
        uint4 AL0 = g_xf_lo[(f0*32 + c)*32 + lane];
        uint4 AH1 = g_xf_hi[((f0+1)*32 + c)*32 + lane];
        uint4 AL1 = g_xf_lo[((f0+1)*32 + c)*32 + lane];
        #pragma unroll
        for (int nf = 0; nf < 8; nf++){
            uint4 W = g_w1f[((h*32 + c)*8 + nf)*32 + lane];
            mma_bf16(acc[0][nf], (const uint32_t*)&AH0, W.x, W.y);
            mma_bf16(acc[0][nf], (const uint32_t*)&AH0, W.z, W.w);
            mma_bf16(acc[0][nf], (const uint32_t*)&AL0, W.x, W.y);
            mma_bf16(acc[1][nf], (const uint32_t*)&AH1, W.x, W.y);
            mma_bf16(acc[1][nf], (const uint32_t*)&AH1, W.z, W.w);
            mma_bf16(acc[1][nf], (const uint32_t*)&AL1, W.x, W.y);
        }
    }

    int rA = wid*32 + (lane>>2);
    #pragma unroll
    for (int fr = 0; fr < 2; fr++){
        int row0 = rA + 16*fr, row1 = row0 + 8;
        #pragma unroll
        for (int nf = 0; nf < 8; nf++){
            int c0 = nf*8 + tig*2;
            *(float2*)&g_Wh[(size_t)(i0+row0)*FF + h*DH + c0] = make_float2(acc[fr][nf][0], acc[fr][nf][1]);
            *(float2*)&g_Wh[(size_t)(i0+row1)*FF + h*DH + c0] = make_float2(acc[fr][nf][2], acc[fr][nf][3]);
            Ts[row0*68 + c0] = acc[fr][nf][0]; Ts[row0*68 + c0+1] = acc[fr][nf][1];
            Ts[row1*68 + c0] = acc[fr][nf][2]; Ts[row1*68 + c0+1] = acc[fr][nf][3];
        }
    }
    __syncthreads();
    #pragma unroll
    for (int e = 0; e < 16; e++){
        int eid = e*256 + tid;
        int fh = eid>>5, ln = eid&31;
        int jc = fh>>3, nf = fh&7;
        int jl = jc*16 + (ln&3)*2;
        int d  = nf*8 + (ln>>2);
        float v0 = Ts[jl*68 + d], v1 = Ts[(jl+1)*68 + d];
        float v2 = Ts[(jl+8)*68 + d], v3 = Ts[(jl+9)*68 + d];
        uint32_t h01 = bf2pack(v0, v1), h89 = bf2pack(v2, v3);
        uint32_t l01 = bf2pack(v0 - bflow(h01), v1 - bfhigh(h01));
        uint32_t l89 = bf2pack(v2 - bflow(h89), v3 - bfhigh(h89));
        g_whf[((h*256 + (i0>>4) + jc)*8 + nf)*32 + ln] = make_uint4(h01, h89, l01, l89);
    }
}

// ====== kernel 2: layer-1 f/e tables ======
__global__ void k_f1(const float* __restrict__ a1){
    int g = blockIdx.x*8 + (threadIdx.x>>5);
    int lane = threadIdx.x & 31;
    int h = g >> 12;
    int i = g & (NN-1);
    const float* wh = g_Wh + (size_t)i*FF + h*DH;
    const float* as = a1 + h*2*DH;
    const float* ad = as + DH;
    float p1 = wh[lane]*as[lane] + wh[lane+32]*as[lane+32];
    float p2 = wh[lane]*ad[lane] + wh[lane+32]*ad[lane+32];
    #pragma unroll
    for (int o = 16; o; o >>= 1){
        p1 += __shfl_xor_sync(0xffffffffu, p1, o);
        p2 += __shfl_xor_sync(0xffffffffu, p2, o);
    }
    if (lane == 0){
        int k = h*NN + i;
        g_t1[k] = make_float4(expf(p1), expf(LRA*p1), p1, 0.f);
        g_t2[k] = make_float4(expf(p2), expf(LRA*p2), p2, 0.f);
    }
}

// === kernel 3: layer-1 attention, HMMA hi/lo, no smem, j-split x2 ===
__global__ void __launch_bounds__(256, 2) k_att1h(){
    int tid = threadIdx.x, wid = tid>>5, lane = tid&31;
    int h = blockIdx.x, i0 = blockIdx.y*256, jh = blockIdx.z;
    int tig = lane & 3;
    int rA = wid*32 + (lane>>2);

    float e1p[4], e1n[4], f1v[4], ds[4];
    #pragma unroll
    for (int k = 0; k < 4; k++){
        float4 tv = g_t1[h*NN + i0 + rA + 8*k];
        e1p[k] = tv.x; e1n[k] = tv.y; f1v[k] = tv.z; ds[k] = 0.f;
    }

    float acc[2][8][4];
    #pragma unroll
    for (int fr = 0; fr < 2; fr++)
        #pragma unroll
        for (int nf = 0; nf < 8; nf++)
            acc[fr][nf][0]=acc[fr][nf][1]=acc[fr][nf][2]=acc[fr][nf][3]=0.f;

    #pragma unroll 1
    for (int tl = 0; tl < 16; tl++){
        int j0 = jh*2048 + tl*128;
        #pragma unroll 2
        for (int c = 0; c < 8; c++){
            int p0 = c*16 + tig*2;
            float4 tc0 = g_t2[h*NN + j0 + p0];
            float4 tc1 = g_t2[h*NN + j0 + p0 + 1];
            float4 tc2 = g_t2[h*NN + j0 + p0 + 8];
            float4 tc3 = g_t2[h*NN + j0 + p0 + 9];
            int b0 = tig*2, b1 = b0+1, b2 = b0+8, b3 = b0+9;

            float v[4][4];
            #pragma unroll
            for (int k = 0; k < 4; k++){
                uint32_t wb = g_adjbit[(size_t)(i0+rA+8*k)*128 + (j0>>5) + (c>>1)] >> ((c&1)*16);
                PV(tc0, e1p[k], e1n[k], f1v[k], wb, b0, v[k][0]);
                PV(tc1, e1p[k], e1n[k], f1v[k], wb, b1, v[k][1]);
                PV(tc2, e1p[k], e1n[k], f1v[k], wb, b2, v[k][2]);
                PV(tc3, e1p[k], e1n[k], f1v[k], wb, b3, v[k][3]);
                ds[k] += (v[k][0]+v[k][1]) + (v[k][2]+v[k][3]);
            }

            uint32_t ah0[4], al0[4], ah1[4], al1[4];
            ah0[0] = bf2pack(v[0][0], v[0][1]); ah0[1] = bf2pack(v[1][0], v[1][1]);
            ah0[2] = bf2pack(v[0][2], v[0][3]); ah0[3] = bf2pack(v[1][2], v[1][3]);
            ah1[0] = bf2pack(v[2][0], v[2][1]); ah1[1] = bf2pack(v[3][0], v[3][1]);
            ah1[2] = bf2pack(v[2][2], v[2][3]); ah1[3] = bf2pack(v[3][2], v[3][3]);
            al0[0] = bf2pack(v[0][0]-bflow(ah0[0]), v[0][1]-bfhigh(ah0[0]));
            al0[1] = bf2pack(v[1][0]-bflow(ah0[1]), v[1][1]-bfhigh(ah0[1]));
            al0[2] = bf2pack(v[0][2]-bflow(ah0[2]), v[0][3]-bfhigh(ah0[2]));
            al0[3] = bf2pack(v[1][2]-bflow(ah0[3]), v[1][3]-bfhigh(ah0[3]));
            al1[0] = bf2pack(v[2][0]-bflow(ah1[0]), v[2][1]-bfhigh(ah1[0]));
            al1[1] = bf2pack(v[3][0]-bflow(ah1[1]), v[3][1]-bfhigh(ah1[1]));
            al1[2] = bf2pack(v[2][2]-bflow(ah1[2]), v[2][3]-bfhigh(ah1[2]));
            al1[3] = bf2pack(v[3][2]-bflow(ah1[3]), v[3][3]-bfhigh(ah1[3]));

            int jcg = (j0>>4) + c;
            const uint4* Wp = &g_whf[((h*256 + jcg)*8)*32 + lane];
            #pragma unroll
            for (int nf = 0; nf < 8; nf++){
                uint4 W = Wp[nf*32];
                mma_bf16(acc[0][nf], ah0, W.x, W.y);
                mma_bf16(acc[0][nf], ah0, W.z, W.w);
                mma_bf16(acc[0][nf], al0, W.x, W.y);
                mma_bf16(acc[1][nf], ah1, W.x, W.y);
                mma_bf16(acc[1][nf], ah1, W.z, W.w);
                mma_bf16(acc[1][nf], al1, W.x, W.y);
            }
        }
    }

    #pragma unroll
    for (int k = 0; k < 4; k++){
        ds[k] += __shfl_xor_sync(0xffffffffu, ds[k], 1);
        ds[k] += __shfl_xor_sync(0xffffffffu, ds[k], 2);
    }
    if (tig == 0){
        #pragma unroll
        for (int k = 0; k < 4; k++)
            g_pd1[jh*NH*NN + h*NN + i0 + rA + 8*k] = ds[k];
    }

    float* Pb = g_p1 + (size_t)jh*NN*FF;
    #pragma unroll
    for (int fr = 0; fr < 2; fr++){
        float* base0 = &Pb[(size_t)(i0 + rA + 16*fr)*FF + h*DH + tig*2];
        float* base1 = &Pb[(size_t)(i0 + rA + 16*fr + 8)*FF + h*DH + tig*2];
        #pragma unroll
        for (int nf = 0; nf < 8; nf++){
            *(float2*)(base0 + nf*8) = make_float2(acc[fr][nf][0], acc[fr][nf][1]);
            *(float2*)(base1 + nf*8) = make_float2(acc[fr][nf][2], acc[fr][nf][3]);
        }
    }
}

// ====== kernel 3b: merge att1 partials, normalize, ELU -> g_h1 ======
__global__ void k_red1(){
    int idx = blockIdx.x*256 + threadIdx.x;          // 524288
    int i = idx >> 7;
    int c = (idx & 127) * 4;
    int h = c >> 6;
    float dsum = g_pd1[h*NN + i] + g_pd1[NH*NN + h*NN + i];
    float inv = 1.0f / dsum;
    float4 a = *(const float4*)&g_p1[(size_t)i*FF + c];
    float4 b = *(const float4*)&g_p1[(size_t)NN*FF + (size_t)i*FF + c];
    float4 o;
    o.x = elu1((a.x + b.x) * inv);
    o.y = elu1((a.y + b.y) * inv);
    o.z = elu1((a.z + b.z) * inv);
    o.w = elu1((a.w + b.w) * inv);
    *(float4*)&g_h1[(size_t)i*FF + c] = o;
}

// ========== kernel 4: Wh2 = h1 @ Wo + fp32 store + bf16 hi/lo transpose ==========
__global__ void k_gemm2(const float* __restrict__ Wo){
    __shared__ float As[32][65];
    __shared__ float Bs[64][40];
    __shared__ float Tw[40][33];
    int tid = threadIdx.x;
    int row = tid & 31, cg = tid >> 5;
    int i0 = blockIdx.x*32;
    float acc[5] = {};
    for (int k0 = 0; k0 < FF; k0 += 64){
        __syncthreads();
        #pragma unroll
        for (int t = 0; t < 8; t++){
            int idx = tid + t*256;
            int rr = idx>>6, c = idx&63;
            As[rr&31][c] = g_h1[(size_t)(i0+rr)*FF + k0 + c];
        }
        for (int idx = tid; idx < 64*NC; idx += 256){
            int rr = idx/NC, c = idx - rr*NC;
            Bs[rr][c] = Wo[(size_t)(k0+rr)*NC + c];
        }
        __syncthreads();
        #pragma unroll 8
        for (int kk = 0; kk < 64; kk++){
            float a = As[row][kk];
            #pragma unroll
            for (int q = 0; q < 5; q++) acc[q] += a * Bs[kk][cg*5+q];
        }
    }
    #pragma unroll
    for (int q = 0; q < 5; q++){
        g_Wh2[(size_t)(i0+row)*NC + cg*5 + q] = acc[q];
        Tw[cg*5+q][row] = acc[q];
    }
    __syncthreads();
    for (int e = tid; e < NC*32; e += 256){
        int d = e>>5, il = e&31;
        float v = Tw[d][il];
        __nv_bfloat16 hb = __float2bfloat16(v);
        __nv_bfloat16 lb = __float2bfloat16(v - __bfloat162float(hb));
        g_W2T_hi[(size_t)d*NN + i0 + il] = hb;
        g_W2T_lo[(size_t)d*NN + i0 + il] = lb;
    }
}

// ====== kernel 5: layer-2 f/e tables ======
__global__ void k_f2b(const float* __restrict__ ao){
    int g = blockIdx.x*8 + (threadIdx.x>>5);
    int lane = threadIdx.x & 31;
    const float* w = g_Wh2 + (size_t)g*NC;
    float v  = w[lane];
    float p1 = v*ao[lane];
    float p2 = v*ao[NC+lane];
    if (lane < 8){
        float v2 = w[32+lane];
        p1 += v2*ao[32+lane];
        p2 += v2*ao[NC+32+lane];
    }
    #pragma unroll
    for (int o = 16; o; o >>= 1){
        p1 += __shfl_xor_sync(0xffffffffu, p1, o);
        p2 += __shfl_xor_sync(0xffffffffu, p2, o);
    }
    if (lane == 0){
        g_t1b[g] = make_float4(expf(p1), expf(LRA*p1), p1, 0.f);
        g_t2b[g] = make_float4(expf(p2), expf(LRA*p2), p2, 0.f);
    }
}

// === kernel 6: layer-2 attention, HMMA hi/lo, j-split x4 ===
__global__ void __launch_bounds__(256) k_att2_mma(){
    __shared__ float4 s_tbl[128];
    __shared__ uint4 s_adj[128];
    __shared__ uint2 Wf_hi[40][32];
    __shared__ uint2 Wf_lo[40][32];

    int tid = threadIdx.x, wid = tid>>5, lane = tid&31;
    int i0 = blockIdx.x*128, js = blockIdx.y;
    int tig = lane & 3;
    int r0l = wid*16 + (lane>>2);
    int r1l = r0l + 8;

    float4 t1a = g_t1b[i0 + r0l];
    float4 t1b = g_t1b[i0 + r1l];
    float e1p0=t1a.x, e1n0=t1a.y, f10=t1a.z;
    float e1p1=t1b.x, e1n1=t1b.y, f11=t1b.z;
    float ds0 = 0.f, ds1 = 0.f;

    float acc[5][4];
    #pragma unroll
    for (int nf = 0; nf < 5; nf++){ acc[nf][0]=acc[nf][1]=acc[nf][2]=acc[nf][3]=0.f; }

    #pragma unroll 1
    for (int t = js*8; t < js*8 + 8; t++){
        int j0 = t*128;
        __syncthreads();
        if (tid < 128){
            s_tbl[tid] = g_t2b[j0 + tid];
            s_adj[tid] = *(const uint4*)(g_adjbit2 + (size_t)(i0+tid)*128 + t*4);
        }
        #pragma unroll
        for (int q = 0; q < 5; q++){
            int e = q*256 + tid;
            int fh = e>>5, ln = e&31;
            int nf = fh>>3, c = fh&7;
            int d = nf*8 + (ln>>2);
            int jj = c*16 + (ln&3)*2;
            size_t src = (size_t)d*NN + j0 + jj;
            Wf_hi[fh][ln] = make_uint2(*(const uint32_t*)(g_W2T_hi + src),
                                       *(const uint32_t*)(g_W2T_hi + src + 8));
            Wf_lo[fh][ln] = make_uint2(*(const uint32_t*)(g_W2T_lo + src),
                                       *(const uint32_t*)(g_W2T_lo + src + 8));
        }
        __syncthreads();

        #pragma unroll 2
        for (int c = 0; c < 8; c++){
            int p0 = c*16 + tig*2;
            float4 ta = s_tbl[p0], tb = s_tbl[p0+1], tc = s_tbl[p0+8], td = s_tbl[p0+9];
            uint32_t w0 = ((const uint32_t*)&s_adj[r0l])[c>>1] >> ((c&1)*16);
            uint32_t w1 = ((const uint32_t*)&s_adj[r1l])[c>>1] >> ((c&1)*16);
            int b0 = tig*2, b1 = b0+1, b2 = b0+8, b3 = b0+9;

            float v00,v01,v02,v03, v10,v11,v12,v13;
            PV(ta,e1p0,e1n0,f10,w0,b0,v00); PV(tb,e1p0,e1n0,f10,w0,b1,v01);
            PV(tc,e1p0,e1n0,f10,w0,b2,v02); PV(td,e1p0,e1n0,f10,w0,b3,v03);
            PV(ta,e1p1,e1n1,f11,w1,b0,v10); PV(tb,e1p1,e1n1,f11,w1,b1,v11);
            PV(tc,e1p1,e1n1,f11,w1,b2,v12); PV(td,e1p1,e1n1,f11,w1,b3,v13);
            ds0 += (v00+v01)+(v02+v03);
            ds1 += (v10+v11)+(v12+v13);

            uint32_t ah[4], al[4];
            ah[0] = bf2pack(v00, v01); ah[1] = bf2pack(v10, v11);
            ah[2] = bf2pack(v02, v03); ah[3] = bf2pack(v12, v13);
            al[0] = bf2pack(v00 - bflow(ah[0]), v01 - bfhigh(ah[0]));
            al[1] = bf2pack(v10 - bflow(ah[1]), v11 - bfhigh(ah[1]));
            al[2] = bf2pack(v02 - bflow(ah[2]), v03 - bfhigh(ah[2]));
            al[3] = bf2pack(v12 - bflow(ah[3]), v13 - bfhigh(ah[3]));

            #pragma unroll
            for (int nf = 0; nf < 5; nf++){
                uint2 bh = Wf_hi[nf*8+c][lane];
                uint2 bl = Wf_lo[nf*8+c][lane];
                mma_bf16(acc[nf], ah, bh.x, bh.y);
                mma_bf16(acc[nf], ah, bl.x, bl.y);
                mma_bf16(acc[nf], al, bh.x, bh.y);
            }
        }
    }

    ds0 += __shfl_xor_sync(0xffffffffu, ds0, 1);
    ds0 += __shfl_xor_sync(0xffffffffu, ds0, 2);
    ds1 += __shfl_xor_sync(0xffffffffu, ds1, 1);
    ds1 += __shfl_xor_sync(0xffffffffu, ds1, 2);
    if (tig == 0){
        g_pd2[js*NN + i0 + r0l] = ds0;
        g_pd2[js*NN + i0 + r1l] = ds1;
    }

    float* Pb = g_p2 + (size_t)js*NN*NC;
    float* base0 = &Pb[(size_t)(i0+r0l)*NC + tig*2];
    float* base1 = &Pb[(size_t)(i0+r1l)*NC + tig*2];
    #pragma unroll
    for (int nf = 0; nf < 5; nf++){
        *(float2*)(base0 + nf*8) = make_float2(acc[nf][0], acc[nf][1]);
        *(float2*)(base1 + nf*8) = make_float2(acc[nf][2], acc[nf][3]);
    }
}

// ====== kernel 6b: merge att2 partials ======
__global__ void k_red2(){
    int idx = blockIdx.x*256 + threadIdx.x;          // 163840
    int i = idx / NC;
    int c = idx - i*NC;
    float dsum = g_pd2[i] + g_pd2[NN+i] + g_pd2[2*NN+i] + g_pd2[3*NN+i];
    float inv = 1.0f / dsum;
    float v = g_p2[(size_t)i*NC + c] + g_p2[(size_t)NN*NC + i*NC + c]
            + g_p2[(size_t)2*NN*NC + i*NC + c] + g_p2[(size_t)3*NN*NC + i*NC + c];
    g_out2[(size_t)i*NC + c] = v * inv;
}

// ====== kernel 7: outer ELU + log_softmax (one warp per row) ======
__global__ void k_final(float* __restrict__ out){
    int w = threadIdx.x>>5, lane = threadIdx.x & 31;
    int i = blockIdx.x*8 + w;
    float v0 = elu1(g_out2[(size_t)i*NC + lane]);
    float v1 = (lane < 8) ? elu1(g_out2[(size_t)i*NC + 32 + lane]) : -1e30f;
    float m = fmaxf(v0, v1);
    #pragma unroll
    for (int o = 16; o; o >>= 1) m = fmaxf(m, __shfl_xor_sync(0xffffffffu, m, o));
    float s = expf(v0 - m) + ((lane < 8) ? expf(v1 - m) : 0.f);
    #pragma unroll
    for (int o = 16; o; o >>= 1) s += __shfl_xor_sync(0xffffffffu, s, o);
    float ls = m + logf(s);
    out[(size_t)i*NC + lane] = v0 - ls;
    if (lane < 8) out[(size_t)i*NC + 32 + lane] = v1 - ls;
}

// ============================== launch ==============================
extern "C" void kernel_launch(void* const* d_in, const int* in_sizes, int n_in,
                              void* d_out, int out_size){
    const float* x  = (const float*)d_in[0];
    const int*   adj= (const int*)  d_in[1];
    const float* W1 = (const float*)d_in[2];
    const float* a1 = (const float*)d_in[3];
    const float* Wo = (const float*)d_in[4];
    const float* ao = (const float*)d_in[5];
    float* out = (float*)d_out;

    static int smem_set = 0;
    if (!smem_set){
        cudaFuncSetAttribute(k_gemm1h, cudaFuncAttributeMaxDynamicSharedMemorySize, 256*68*4);
        smem_set = 1;
    }

    k_pack   <<<dim3(2048, 2), 256>>>(adj);
    k_xsplit <<<1024, 256>>>(x);
    k_w1split<<<256, 256>>>(W1);
    k_gemm1h <<<dim3(16, 8), 256, 256*68*4>>>();
    k_f1     <<<4096, 256>>>(a1);
    k_att1h  <<<dim3(8, 16, 2), 256>>>();
    k_red1   <<<2048, 256>>>();
    k_gemm2  <<<128, 256>>>(Wo);
    k_f2b    <<<512, 256>>>(ao);
    k_att2_mma<<<dim3(32, 4), 256>>>();
    k_red2   <<<640, 256>>>();
    k_final  <<<512, 256>>>(out);
}